// round 1
// baseline (speedup 1.0000x reference)
#include <cuda_runtime.h>
#include <cuda_bf16.h>
#include <cstdint>

#define MTOK 8192      // NUM_EXPERTS * TOKENS_PER_EXPERT
#define HID  2048
#define DEX  4096
#define RK   64
#define K1E  (3*HID)   // 6144  expanded K for hidden dim
#define K2E  (3*DEX)   // 12288 expanded K for expert dim
#define KRE  (3*RK)    // 192   expanded K for LoRA rank

// ---------------- scratch (device globals: allowed, no runtime alloc) -------
__device__ __align__(16) __nv_bfloat16 g_Xe  [(size_t)MTOK * K1E];
__device__ __align__(16) __nv_bfloat16 g_Wgue[(size_t)2*DEX * K1E];
__device__ __align__(16) __nv_bfloat16 g_Ague[(size_t)RK * K1E];
__device__ __align__(16) __nv_bfloat16 g_Bgue[(size_t)2*DEX * KRE];
__device__ __align__(16) __nv_bfloat16 g_Wde [(size_t)HID * K2E];
__device__ __align__(16) __nv_bfloat16 g_Ade [(size_t)RK * K2E];
__device__ __align__(16) __nv_bfloat16 g_Bde [(size_t)HID * KRE];
__device__ __align__(16) float         g_T1  [(size_t)MTOK * RK];
__device__ __align__(16) __nv_bfloat16 g_T1e [(size_t)MTOK * KRE];
__device__ __align__(16) float         g_T2  [(size_t)MTOK * RK];
__device__ __align__(16) __nv_bfloat16 g_T2e [(size_t)MTOK * KRE];
__device__ __align__(16) float         g_GU  [(size_t)MTOK * 2*DEX];
__device__ __align__(16) __nv_bfloat16 g_He  [(size_t)MTOK * K2E];

// ---------------- fp32 -> bf16 [hi,lo,hi] / [hi,hi,lo] expansion ------------
// A-side triple [hi,lo,hi] paired with B-side [hi,hi,lo] gives
// hi*hi + lo*hi + hi*lo per logical k — ~fp32-accurate bf16 GEMM.
template<bool ASIDE>
__global__ void cvt_expand(const float* __restrict__ in,
                           __nv_bfloat16* __restrict__ out,
                           size_t n, float scale) {
    size_t i = (size_t)blockIdx.x * blockDim.x + threadIdx.x;
    if (i >= n) return;
    float x = in[i] * scale;
    __nv_bfloat16 hi = __float2bfloat16(x);
    float lof = x - __bfloat162float(hi);
    __nv_bfloat16 lo = __float2bfloat16(lof);
    size_t o = 3 * i;
    if (ASIDE) { out[o] = hi; out[o+1] = lo; out[o+2] = hi; }
    else       { out[o] = hi; out[o+1] = hi; out[o+2] = lo; }
}

// ---------------- SwiGLU + expansion (A-side, H feeds GEMM2 as A) -----------
__global__ void swiglu_expand(const float* __restrict__ gu,
                              __nv_bfloat16* __restrict__ he) {
    size_t i = (size_t)blockIdx.x * blockDim.x + threadIdx.x;
    if (i >= (size_t)MTOK * DEX) return;
    size_t m = i / DEX;
    size_t d = i - m * DEX;
    const float* row = gu + m * (size_t)(2 * DEX);
    float g = row[d];
    float u = row[DEX + d];
    float h = u * g / (1.0f + __expf(-g));
    __nv_bfloat16 hi = __float2bfloat16(h);
    float lof = h - __bfloat162float(hi);
    size_t o = 3 * i;
    he[o] = hi; he[o+1] = __float2bfloat16(lof); he[o+2] = hi;
}

// ---------------- bf16 TN GEMM, C[m,n] = sum_k A[m,k]*B[n,k] (+ tail seg) ---
#define BM 128
#define BN 128
#define BKK 64
#define STAGES 4
#define NTH 256
#define TILE_BYTES (BM * BKK * 2)       // 16 KB
#define SMEM_BYTES (2 * STAGES * TILE_BYTES)  // 128 KB

__device__ __forceinline__ void load_tiles(uint32_t smem_u32, int stage,
                                           const __nv_bfloat16* gA,
                                           const __nv_bfloat16* gB,
                                           int m0, int n0, int N, int Ks,
                                           int kt, int tid) {
#pragma unroll
    for (int i = 0; i < 4; i++) {
        int c = tid + i * NTH;          // 0..1023 chunk id (16B chunks)
        int row = c >> 3;
        int col = c & 7;
        uint32_t sw = (uint32_t)(col ^ (row & 7)) << 4;
        uint32_t da = smem_u32 + (uint32_t)stage * TILE_BYTES + row * 128 + sw;
        const void* sa = (const void*)(gA + (size_t)(m0 + row) * Ks
                                          + (size_t)kt * BKK + col * 8);
        asm volatile("cp.async.cg.shared.global [%0], [%1], 16;"
                     :: "r"(da), "l"(sa));
        int brow = n0 + row; brow = brow < N ? brow : N - 1;   // clamp (N=64 case)
        uint32_t db = smem_u32 + (uint32_t)(STAGES + stage) * TILE_BYTES
                               + row * 128 + sw;
        const void* sb = (const void*)(gB + (size_t)brow * Ks
                                          + (size_t)kt * BKK + col * 8);
        asm volatile("cp.async.cg.shared.global [%0], [%1], 16;"
                     :: "r"(db), "l"(sb));
    }
}

__global__ __launch_bounds__(NTH) void gemm_bf16x3(
    const __nv_bfloat16* __restrict__ A,  const __nv_bfloat16* __restrict__ B,
    const __nv_bfloat16* __restrict__ A2, const __nv_bfloat16* __restrict__ B2,
    float* __restrict__ C, int M, int N, int K, int Kt) {
    extern __shared__ char smem[];
    const uint32_t smem_u32 = (uint32_t)__cvta_generic_to_shared(smem);
    const int tid  = threadIdx.x;
    const int warp = tid >> 5, lane = tid & 31;
    const int wm = warp >> 2, wn = warp & 3;   // 2 x 4 warp grid -> 64x32 warp tile
    const int gid = lane >> 2, tig = lane & 3;
    const int m0 = blockIdx.y * BM;
    const int n0 = blockIdx.x * BN;

    float acc[4][4][4];
#pragma unroll
    for (int a = 0; a < 4; a++)
#pragma unroll
        for (int b = 0; b < 4; b++)
#pragma unroll
            for (int c = 0; c < 4; c++) acc[a][b][c] = 0.0f;

    for (int seg = 0; seg < 2; seg++) {
        const __nv_bfloat16* gA = seg ? A2 : A;
        const __nv_bfloat16* gB = seg ? B2 : B;
        const int Ks = seg ? Kt : K;
        if (Ks == 0) break;
        const int ktiles = Ks / BKK;

        // prologue: STAGES-1 groups (empty commits keep group accounting uniform)
        for (int p = 0; p < STAGES - 1; p++) {
            if (p < ktiles)
                load_tiles(smem_u32, p, gA, gB, m0, n0, N, Ks, p, tid);
            asm volatile("cp.async.commit_group;");
        }

        for (int kt = 0; kt < ktiles; kt++) {
            asm volatile("cp.async.wait_group %0;" :: "n"(STAGES - 2));
            __syncthreads();
            int nk = kt + STAGES - 1;
            if (nk < ktiles)
                load_tiles(smem_u32, nk % STAGES, gA, gB, m0, n0, N, Ks, nk, tid);
            asm volatile("cp.async.commit_group;");

            const int st = kt % STAGES;
            const uint32_t sA = smem_u32 + (uint32_t)st * TILE_BYTES;
            const uint32_t sB = smem_u32 + (uint32_t)(STAGES + st) * TILE_BYTES;
#pragma unroll
            for (int kk = 0; kk < BKK; kk += 16) {
                uint32_t ra[4][4];
#pragma unroll
                for (int mi = 0; mi < 4; mi++) {
                    int row = wm * 64 + mi * 16 + (lane & 15);
                    int ch  = (kk >> 3) + (lane >> 4);
                    uint32_t ad = sA + row * 128 + ((uint32_t)(ch ^ (row & 7)) << 4);
                    asm volatile(
                        "ldmatrix.sync.aligned.m8n8.x4.shared.b16 {%0,%1,%2,%3}, [%4];"
                        : "=r"(ra[mi][0]), "=r"(ra[mi][1]),
                          "=r"(ra[mi][2]), "=r"(ra[mi][3])
                        : "r"(ad));
                }
                uint32_t rb[4][2];
#pragma unroll
                for (int ni = 0; ni < 4; ni++) {
                    int n = wn * 32 + ni * 8 + gid;
                    int ch0 = kk >> 3;
                    uint32_t b0 = sB + n * 128 + ((uint32_t)(ch0 ^ (n & 7)) << 4) + tig * 4;
                    uint32_t b1 = sB + n * 128 + ((uint32_t)((ch0 + 1) ^ (n & 7)) << 4) + tig * 4;
                    asm volatile("ld.shared.b32 %0, [%1];" : "=r"(rb[ni][0]) : "r"(b0));
                    asm volatile("ld.shared.b32 %0, [%1];" : "=r"(rb[ni][1]) : "r"(b1));
                }
#pragma unroll
                for (int mi = 0; mi < 4; mi++)
#pragma unroll
                    for (int ni = 0; ni < 4; ni++)
                        asm volatile(
                            "mma.sync.aligned.m16n8k16.row.col.f32.bf16.bf16.f32 "
                            "{%0,%1,%2,%3}, {%4,%5,%6,%7}, {%8,%9}, {%0,%1,%2,%3};"
                            : "+f"(acc[mi][ni][0]), "+f"(acc[mi][ni][1]),
                              "+f"(acc[mi][ni][2]), "+f"(acc[mi][ni][3])
                            : "r"(ra[mi][0]), "r"(ra[mi][1]),
                              "r"(ra[mi][2]), "r"(ra[mi][3]),
                              "r"(rb[ni][0]), "r"(rb[ni][1]));
            }
        }
        asm volatile("cp.async.wait_group 0;");
        __syncthreads();
    }

    // epilogue
#pragma unroll
    for (int mi = 0; mi < 4; mi++) {
        int r0 = m0 + wm * 64 + mi * 16 + gid;
#pragma unroll
        for (int ni = 0; ni < 4; ni++) {
            int c0 = n0 + wn * 32 + ni * 8 + tig * 2;
            if (c0 < N) {
                float2 v0 = make_float2(acc[mi][ni][0], acc[mi][ni][1]);
                float2 v1 = make_float2(acc[mi][ni][2], acc[mi][ni][3]);
                *reinterpret_cast<float2*>(C + (size_t)r0 * N + c0) = v0;
                *reinterpret_cast<float2*>(C + (size_t)(r0 + 8) * N + c0) = v1;
            }
        }
    }
}

// ---------------- launcher ---------------------------------------------------
extern "C" void kernel_launch(void* const* d_in, const int* in_sizes, int n_in,
                              void* d_out, int out_size) {
    const float* X   = (const float*)d_in[0];
    const float* Wgu = (const float*)d_in[1];
    const float* Agu = (const float*)d_in[2];
    const float* Bgu = (const float*)d_in[3];
    const float* Wd  = (const float*)d_in[4];
    const float* Ad  = (const float*)d_in[5];
    const float* Bd  = (const float*)d_in[6];
    float* out = (float*)d_out;

    __nv_bfloat16 *Xe, *Wgue, *Ague, *Bgue, *Wde, *Ade, *Bde, *T1e, *T2e, *He;
    float *T1, *T2, *GU;
    cudaGetSymbolAddress((void**)&Xe,   g_Xe);
    cudaGetSymbolAddress((void**)&Wgue, g_Wgue);
    cudaGetSymbolAddress((void**)&Ague, g_Ague);
    cudaGetSymbolAddress((void**)&Bgue, g_Bgue);
    cudaGetSymbolAddress((void**)&Wde,  g_Wde);
    cudaGetSymbolAddress((void**)&Ade,  g_Ade);
    cudaGetSymbolAddress((void**)&Bde,  g_Bde);
    cudaGetSymbolAddress((void**)&T1,   g_T1);
    cudaGetSymbolAddress((void**)&T1e,  g_T1e);
    cudaGetSymbolAddress((void**)&T2,   g_T2);
    cudaGetSymbolAddress((void**)&T2e,  g_T2e);
    cudaGetSymbolAddress((void**)&GU,   g_GU);
    cudaGetSymbolAddress((void**)&He,   g_He);

    cudaFuncSetAttribute(gemm_bf16x3,
                         cudaFuncAttributeMaxDynamicSharedMemorySize, SMEM_BYTES);

    const int T = 256;
    // expand inputs
    { size_t n = (size_t)MTOK * HID;
      cvt_expand<true ><<<(unsigned)((n + T - 1) / T), T>>>(X, Xe, n, 1.0f); }
    { size_t n = (size_t)2 * DEX * HID;
      cvt_expand<false><<<(unsigned)((n + T - 1) / T), T>>>(Wgu, Wgue, n, 1.0f); }
    { size_t n = (size_t)RK * HID;
      cvt_expand<false><<<(unsigned)((n + T - 1) / T), T>>>(Agu, Ague, n, 1.0f); }
    { size_t n = (size_t)2 * DEX * RK;
      cvt_expand<false><<<(unsigned)((n + T - 1) / T), T>>>(Bgu, Bgue, n, 1.0f); }
    { size_t n = (size_t)HID * DEX;
      cvt_expand<false><<<(unsigned)((n + T - 1) / T), T>>>(Wd, Wde, n, 1.0f); }
    { size_t n = (size_t)RK * DEX;
      cvt_expand<false><<<(unsigned)((n + T - 1) / T), T>>>(Ad, Ade, n, 1.0f); }
    { size_t n = (size_t)HID * RK;
      cvt_expand<false><<<(unsigned)((n + T - 1) / T), T>>>(Bd, Bde, n, 1.0f); }

    dim3 blk(NTH);

    // T1 = X @ A_gu^T  (M=8192, N=64, K'=6144)
    gemm_bf16x3<<<dim3(1, MTOK / BM), blk, SMEM_BYTES>>>(
        Xe, Ague, nullptr, nullptr, T1, MTOK, RK, K1E, 0);
    { size_t n = (size_t)MTOK * RK;   // fold scaling = 16/64 = 0.25 exactly
      cvt_expand<true ><<<(unsigned)((n + T - 1) / T), T>>>(T1, T1e, n, 0.25f); }

    // GU = X @ W_gu^T + T1s @ B_gu^T  (M=8192, N=8192)
    gemm_bf16x3<<<dim3(2 * DEX / BN, MTOK / BM), blk, SMEM_BYTES>>>(
        Xe, Wgue, T1e, Bgue, GU, MTOK, 2 * DEX, K1E, KRE);

    // H = up * silu(gate), expanded
    { size_t n = (size_t)MTOK * DEX;
      swiglu_expand<<<(unsigned)((n + T - 1) / T), T>>>(GU, He); }

    // T2 = H @ A_d^T  (M=8192, N=64, K'=12288)
    gemm_bf16x3<<<dim3(1, MTOK / BM), blk, SMEM_BYTES>>>(
        He, Ade, nullptr, nullptr, T2, MTOK, RK, K2E, 0);
    { size_t n = (size_t)MTOK * RK;
      cvt_expand<true ><<<(unsigned)((n + T - 1) / T), T>>>(T2, T2e, n, 0.25f); }

    // out = H @ W_d^T + T2s @ B_d^T  (M=8192, N=2048)
    gemm_bf16x3<<<dim3(HID / BN, MTOK / BM), blk, SMEM_BYTES>>>(
        He, Wde, T2e, Bde, out, MTOK, HID, K2E, KRE);
}

// round 3
// speedup vs baseline: 1.1618x; 1.1618x over previous
#include <cuda_runtime.h>
#include <cuda_bf16.h>
#include <cstdint>

#define MTOK 8192
#define HID  2048
#define DEX  4096
#define RK   64
#define K1E  (3*HID)   // 6144
#define K2E  (3*DEX)   // 12288
#define KRE  (3*RK)    // 192

// ---------------- scratch (device globals) ----------------------------------
__device__ __align__(16) __nv_bfloat16 g_Xe  [(size_t)MTOK * K1E];
__device__ __align__(16) __nv_bfloat16 g_Wgue[(size_t)2*DEX * K1E];
__device__ __align__(16) __nv_bfloat16 g_Ague[(size_t)RK * K1E];
__device__ __align__(16) __nv_bfloat16 g_Bgue[(size_t)2*DEX * KRE];
__device__ __align__(16) __nv_bfloat16 g_Wde [(size_t)HID * K2E];
__device__ __align__(16) __nv_bfloat16 g_Ade [(size_t)RK * K2E];
__device__ __align__(16) __nv_bfloat16 g_Bde [(size_t)HID * KRE];
__device__ __align__(16) float         g_T1  [(size_t)MTOK * RK];
__device__ __align__(16) __nv_bfloat16 g_T1e [(size_t)MTOK * KRE];
__device__ __align__(16) float         g_T2  [(size_t)MTOK * RK];
__device__ __align__(16) __nv_bfloat16 g_T2e [(size_t)MTOK * KRE];
__device__ __align__(16) float         g_GU  [(size_t)MTOK * 2*DEX];
__device__ __align__(16) __nv_bfloat16 g_He  [(size_t)MTOK * K2E];

// ---------------- fp32 -> bf16x3 expansion (8 elems/thread) -----------------
// A-side [hi,lo,hi] x B-side [hi,hi,lo] -> hi*hi + lo*hi + hi*lo per logical k.
template<bool ASIDE>
__global__ void cvt_expand8(const float* __restrict__ in,
                            __nv_bfloat16* __restrict__ out,
                            size_t n8, float scale) {
    size_t i = (size_t)blockIdx.x * blockDim.x + threadIdx.x;
    if (i >= n8) return;
    const float4* p = reinterpret_cast<const float4*>(in) + i * 2;
    float4 v0 = p[0], v1 = p[1];
    float x[8] = {v0.x, v0.y, v0.z, v0.w, v1.x, v1.y, v1.z, v1.w};
    __nv_bfloat16 ob[24];
#pragma unroll
    for (int k = 0; k < 8; k++) {
        float xv = x[k] * scale;
        __nv_bfloat16 hi = __float2bfloat16(xv);
        __nv_bfloat16 lo = __float2bfloat16(xv - __bfloat162float(hi));
        ob[3*k] = hi;
        if (ASIDE) { ob[3*k+1] = lo; ob[3*k+2] = hi; }
        else       { ob[3*k+1] = hi; ob[3*k+2] = lo; }
    }
    uint4* o = reinterpret_cast<uint4*>(out + i * 24);
    const uint4* s = reinterpret_cast<const uint4*>(ob);
    o[0] = s[0]; o[1] = s[1]; o[2] = s[2];
}

// ---------------- SwiGLU + A-side expansion (8 elems/thread) ----------------
__global__ void swiglu_expand8(const float* __restrict__ gu,
                               __nv_bfloat16* __restrict__ he) {
    size_t i = (size_t)blockIdx.x * blockDim.x + threadIdx.x;
    if (i >= (size_t)MTOK * DEX / 8) return;
    size_t base = i * 8;
    size_t m = base / DEX;
    size_t d = base - m * DEX;
    const float4* pg = reinterpret_cast<const float4*>(gu + m * (size_t)(2*DEX) + d);
    const float4* pu = reinterpret_cast<const float4*>(gu + m * (size_t)(2*DEX) + DEX + d);
    float4 g0 = pg[0], g1 = pg[1], u0 = pu[0], u1 = pu[1];
    float gs[8] = {g0.x,g0.y,g0.z,g0.w,g1.x,g1.y,g1.z,g1.w};
    float us[8] = {u0.x,u0.y,u0.z,u0.w,u1.x,u1.y,u1.z,u1.w};
    __nv_bfloat16 ob[24];
#pragma unroll
    for (int k = 0; k < 8; k++) {
        float g = gs[k];
        float h = us[k] * g / (1.0f + __expf(-g));
        __nv_bfloat16 hi = __float2bfloat16(h);
        __nv_bfloat16 lo = __float2bfloat16(h - __bfloat162float(hi));
        ob[3*k] = hi; ob[3*k+1] = lo; ob[3*k+2] = hi;
    }
    uint4* o = reinterpret_cast<uint4*>(he + base * 3);
    const uint4* s = reinterpret_cast<const uint4*>(ob);
    o[0] = s[0]; o[1] = s[1]; o[2] = s[2];
}

// ---------------- bf16 TN GEMM (mma.sync), C = A·B^T (+ LoRA K-tail) --------
#define BM 128
#define BN 128
#define BKK 64
#define STAGES 3
#define NTH 256
#define TILE_BYTES (BM * BKK * 2)              // 16 KB
#define SMEM_BYTES (2 * STAGES * TILE_BYTES)   // 96 KB -> 2 CTAs/SM

__device__ __forceinline__ void load_tiles(uint32_t smem_u32, int stage,
                                           const __nv_bfloat16* gA,
                                           const __nv_bfloat16* gB,
                                           int m0, int n0, int N, int Ks,
                                           int kt, int tid) {
#pragma unroll
    for (int i = 0; i < 4; i++) {
        int c = tid + i * NTH;          // 0..1023 (16B chunks per operand)
        int row = c >> 3;
        int col = c & 7;
        uint32_t sw = (uint32_t)(col ^ (row & 7)) << 4;
        uint32_t da = smem_u32 + (uint32_t)stage * TILE_BYTES + row * 128 + sw;
        const void* sa = (const void*)(gA + (size_t)(m0 + row) * Ks
                                          + (size_t)kt * BKK + col * 8);
        asm volatile("cp.async.cg.shared.global [%0], [%1], 16;"
                     :: "r"(da), "l"(sa));
        int brow = n0 + row; brow = brow < N ? brow : N - 1;   // clamp (N=64 case)
        uint32_t db = smem_u32 + (uint32_t)(STAGES + stage) * TILE_BYTES
                               + row * 128 + sw;
        const void* sb = (const void*)(gB + (size_t)brow * Ks
                                          + (size_t)kt * BKK + col * 8);
        asm volatile("cp.async.cg.shared.global [%0], [%1], 16;"
                     :: "r"(db), "l"(sb));
    }
}

__global__ __launch_bounds__(NTH, 2) void gemm_bf16x3(
    const __nv_bfloat16* __restrict__ A,  const __nv_bfloat16* __restrict__ B,
    const __nv_bfloat16* __restrict__ A2, const __nv_bfloat16* __restrict__ B2,
    float* __restrict__ C, int M, int N, int K, int Kt) {
    extern __shared__ char smem[];
    const uint32_t smem_u32 = (uint32_t)__cvta_generic_to_shared(smem);
    const int tid  = threadIdx.x;
    const int warp = tid >> 5, lane = tid & 31;
    const int wm = warp >> 2, wn = warp & 3;   // 2x4 warps -> 64x32 warp tile
    const int gid = lane >> 2, tig = lane & 3;
    const int m0 = blockIdx.y * BM;
    const int n0 = blockIdx.x * BN;

    float acc[4][4][4];
#pragma unroll
    for (int a = 0; a < 4; a++)
#pragma unroll
        for (int b = 0; b < 4; b++)
#pragma unroll
            for (int c = 0; c < 4; c++) acc[a][b][c] = 0.0f;

    // precomputed fragment-load geometry
    const int a_row_in = (lane & 15);          // + wm*64 + mi*16
    const int a_ch_in  = (lane >> 4);          // + kk>>3
    const int b_row_in = ((lane >> 4) << 3) + (lane & 7);  // + wn*32 + p*16
    const int b_ch_in  = ((lane >> 3) & 1);    // + kk>>3

    for (int seg = 0; seg < 2; seg++) {
        const __nv_bfloat16* gA = seg ? A2 : A;
        const __nv_bfloat16* gB = seg ? B2 : B;
        const int Ks = seg ? Kt : K;
        if (Ks == 0) break;
        const int ktiles = Ks / BKK;

        for (int p = 0; p < STAGES - 1; p++) {
            if (p < ktiles)
                load_tiles(smem_u32, p, gA, gB, m0, n0, N, Ks, p, tid);
            asm volatile("cp.async.commit_group;");
        }

        for (int kt = 0; kt < ktiles; kt++) {
            asm volatile("cp.async.wait_group %0;" :: "n"(STAGES - 2));
            __syncthreads();
            int nk = kt + STAGES - 1;
            if (nk < ktiles)
                load_tiles(smem_u32, nk % STAGES, gA, gB, m0, n0, N, Ks, nk, tid);
            asm volatile("cp.async.commit_group;");

            const int st = kt % STAGES;
            const uint32_t sA = smem_u32 + (uint32_t)st * TILE_BYTES;
            const uint32_t sB = smem_u32 + (uint32_t)(STAGES + st) * TILE_BYTES;
#pragma unroll
            for (int kk = 0; kk < BKK; kk += 16) {
                uint32_t ra[4][4];
#pragma unroll
                for (int mi = 0; mi < 4; mi++) {
                    int row = wm * 64 + mi * 16 + a_row_in;
                    int ch  = (kk >> 3) + a_ch_in;
                    uint32_t ad = sA + row * 128 + ((uint32_t)(ch ^ (row & 7)) << 4);
                    asm volatile(
                        "ldmatrix.sync.aligned.m8n8.x4.shared.b16 {%0,%1,%2,%3}, [%4];"
                        : "=r"(ra[mi][0]), "=r"(ra[mi][1]),
                          "=r"(ra[mi][2]), "=r"(ra[mi][3])
                        : "r"(ad));
                }
                // B frags via ldmatrix.x4: lanes 0-7:(n-lo,k-lo) 8-15:(n-lo,k-hi)
                // 16-23:(n-hi,k-lo) 24-31:(n-hi,k-hi) -> regs {0,1}=n8-tile0,
                // {2,3}=n8-tile1  (matches verified scalar layout of R1)
                uint32_t rb[4][2];
#pragma unroll
                for (int p = 0; p < 2; p++) {
                    int row = wn * 32 + p * 16 + b_row_in;
                    int ch  = (kk >> 3) + b_ch_in;
                    uint32_t bd = sB + row * 128 + ((uint32_t)(ch ^ (row & 7)) << 4);
                    asm volatile(
                        "ldmatrix.sync.aligned.m8n8.x4.shared.b16 {%0,%1,%2,%3}, [%4];"
                        : "=r"(rb[2*p][0]), "=r"(rb[2*p][1]),
                          "=r"(rb[2*p+1][0]), "=r"(rb[2*p+1][1])
                        : "r"(bd));
                }
#pragma unroll
                for (int mi = 0; mi < 4; mi++)
#pragma unroll
                    for (int ni = 0; ni < 4; ni++)
                        asm volatile(
                            "mma.sync.aligned.m16n8k16.row.col.f32.bf16.bf16.f32 "
                            "{%0,%1,%2,%3}, {%4,%5,%6,%7}, {%8,%9}, {%0,%1,%2,%3};"
                            : "+f"(acc[mi][ni][0]), "+f"(acc[mi][ni][1]),
                              "+f"(acc[mi][ni][2]), "+f"(acc[mi][ni][3])
                            : "r"(ra[mi][0]), "r"(ra[mi][1]),
                              "r"(ra[mi][2]), "r"(ra[mi][3]),
                              "r"(rb[ni][0]), "r"(rb[ni][1]));
            }
        }
        asm volatile("cp.async.wait_group 0;");
        __syncthreads();
    }

    // epilogue (verified in R1)
#pragma unroll
    for (int mi = 0; mi < 4; mi++) {
        int r0 = m0 + wm * 64 + mi * 16 + gid;
#pragma unroll
        for (int ni = 0; ni < 4; ni++) {
            int c0 = n0 + wn * 32 + ni * 8 + tig * 2;
            if (c0 < N) {
                float2 v0 = make_float2(acc[mi][ni][0], acc[mi][ni][1]);
                float2 v1 = make_float2(acc[mi][ni][2], acc[mi][ni][3]);
                *reinterpret_cast<float2*>(C + (size_t)r0 * N + c0) = v0;
                *reinterpret_cast<float2*>(C + (size_t)(r0 + 8) * N + c0) = v1;
            }
        }
    }
}

// ---------------- launcher ---------------------------------------------------
extern "C" void kernel_launch(void* const* d_in, const int* in_sizes, int n_in,
                              void* d_out, int out_size) {
    const float* X   = (const float*)d_in[0];
    const float* Wgu = (const float*)d_in[1];
    const float* Agu = (const float*)d_in[2];
    const float* Bgu = (const float*)d_in[3];
    const float* Wd  = (const float*)d_in[4];
    const float* Ad  = (const float*)d_in[5];
    const float* Bd  = (const float*)d_in[6];
    float* out = (float*)d_out;

    __nv_bfloat16 *Xe, *Wgue, *Ague, *Bgue, *Wde, *Ade, *Bde, *T1e, *T2e, *He;
    float *T1, *T2, *GU;
    cudaGetSymbolAddress((void**)&Xe,   g_Xe);
    cudaGetSymbolAddress((void**)&Wgue, g_Wgue);
    cudaGetSymbolAddress((void**)&Ague, g_Ague);
    cudaGetSymbolAddress((void**)&Bgue, g_Bgue);
    cudaGetSymbolAddress((void**)&Wde,  g_Wde);
    cudaGetSymbolAddress((void**)&Ade,  g_Ade);
    cudaGetSymbolAddress((void**)&Bde,  g_Bde);
    cudaGetSymbolAddress((void**)&T1,   g_T1);
    cudaGetSymbolAddress((void**)&T1e,  g_T1e);
    cudaGetSymbolAddress((void**)&T2,   g_T2);
    cudaGetSymbolAddress((void**)&T2e,  g_T2e);
    cudaGetSymbolAddress((void**)&GU,   g_GU);
    cudaGetSymbolAddress((void**)&He,   g_He);

    cudaFuncSetAttribute(gemm_bf16x3,
                         cudaFuncAttributeMaxDynamicSharedMemorySize, SMEM_BYTES);

    const int T = 256;
    auto g8 = [&](size_t n) { return (unsigned)((n / 8 + T - 1) / T); };

    { size_t n = (size_t)MTOK * HID;
      cvt_expand8<true ><<<g8(n), T>>>(X, Xe, n/8, 1.0f); }
    { size_t n = (size_t)2 * DEX * HID;
      cvt_expand8<false><<<g8(n), T>>>(Wgu, Wgue, n/8, 1.0f); }
    { size_t n = (size_t)RK * HID;
      cvt_expand8<false><<<g8(n), T>>>(Agu, Ague, n/8, 1.0f); }
    { size_t n = (size_t)2 * DEX * RK;
      cvt_expand8<false><<<g8(n), T>>>(Bgu, Bgue, n/8, 1.0f); }
    { size_t n = (size_t)HID * DEX;
      cvt_expand8<false><<<g8(n), T>>>(Wd, Wde, n/8, 1.0f); }
    { size_t n = (size_t)RK * DEX;
      cvt_expand8<false><<<g8(n), T>>>(Ad, Ade, n/8, 1.0f); }
    { size_t n = (size_t)HID * RK;
      cvt_expand8<false><<<g8(n), T>>>(Bd, Bde, n/8, 1.0f); }

    dim3 blk(NTH);

    // T1 = X @ A_gu^T   (M=8192, N=64, K=6144)
    gemm_bf16x3<<<dim3(1, MTOK / BM), blk, SMEM_BYTES>>>(
        Xe, Ague, nullptr, nullptr, T1, MTOK, RK, K1E, 0);
    { size_t n = (size_t)MTOK * RK;   // fold scaling 16/64 = 0.25 exactly
      cvt_expand8<true ><<<g8(n), T>>>(T1, T1e, n/8, 0.25f); }

    // GU = X @ W_gu^T + T1s @ B_gu^T   (M=8192, N=8192)
    gemm_bf16x3<<<dim3(2 * DEX / BN, MTOK / BM), blk, SMEM_BYTES>>>(
        Xe, Wgue, T1e, Bgue, GU, MTOK, 2 * DEX, K1E, KRE);

    // H = up * silu(gate), expanded A-side
    { size_t n = (size_t)MTOK * DEX;
      swiglu_expand8<<<g8(n), T>>>(GU, He); }

    // T2 = H @ A_d^T   (M=8192, N=64, K=12288)
    gemm_bf16x3<<<dim3(1, MTOK / BM), blk, SMEM_BYTES>>>(
        He, Ade, nullptr, nullptr, T2, MTOK, RK, K2E, 0);
    { size_t n = (size_t)MTOK * RK;
      cvt_expand8<true ><<<g8(n), T>>>(T2, T2e, n/8, 0.25f); }

    // out = H @ W_d^T + T2s @ B_d^T   (M=8192, N=2048)
    gemm_bf16x3<<<dim3(HID / BN, MTOK / BM), blk, SMEM_BYTES>>>(
        He, Wde, T2e, Bde, out, MTOK, HID, K2E, KRE);
}

// round 5
// speedup vs baseline: 1.2260x; 1.0552x over previous
#include <cuda_runtime.h>
#include <cuda_bf16.h>
#include <cstdint>

#define MTOK 8192
#define HID  2048
#define DEX  4096
#define RK   64
#define K1E  (3*HID)   // 6144
#define K2E  (3*DEX)   // 12288
#define KRE  (3*RK)    // 192
#define SPLITK 4

// ---------------- scratch (device globals) ----------------------------------
__device__ __align__(16) __nv_bfloat16 g_Xe  [(size_t)MTOK * K1E];
__device__ __align__(16) __nv_bfloat16 g_Wgue[(size_t)2*DEX * K1E];
__device__ __align__(16) __nv_bfloat16 g_Ague[(size_t)RK * K1E];
__device__ __align__(16) __nv_bfloat16 g_Bgue[(size_t)2*DEX * KRE];
__device__ __align__(16) __nv_bfloat16 g_Wde [(size_t)HID * K2E];
__device__ __align__(16) __nv_bfloat16 g_Ade [(size_t)RK * K2E];
__device__ __align__(16) __nv_bfloat16 g_Bde [(size_t)HID * KRE];
__device__ __align__(16) float         g_Pk  [(size_t)SPLITK * MTOK * RK];
__device__ __align__(16) __nv_bfloat16 g_T1e [(size_t)MTOK * KRE];
__device__ __align__(16) __nv_bfloat16 g_T2e [(size_t)MTOK * KRE];
__device__ __align__(16) __nv_bfloat16 g_He  [(size_t)MTOK * K2E];

// ---------------- fp32 -> bf16x3 expansion (8 elems/thread) -----------------
// A-side [hi,lo,hi] x B-side [hi,hi,lo] -> hi*hi + lo*hi + hi*lo per logical k.
template<bool ASIDE>
__global__ void cvt_expand8(const float* __restrict__ in,
                            __nv_bfloat16* __restrict__ out,
                            size_t n8, float scale) {
    size_t i = (size_t)blockIdx.x * blockDim.x + threadIdx.x;
    if (i >= n8) return;
    const float4* p = reinterpret_cast<const float4*>(in) + i * 2;
    float4 v0 = p[0], v1 = p[1];
    float x[8] = {v0.x, v0.y, v0.z, v0.w, v1.x, v1.y, v1.z, v1.w};
    __nv_bfloat16 ob[24];
#pragma unroll
    for (int k = 0; k < 8; k++) {
        float xv = x[k] * scale;
        __nv_bfloat16 hi = __float2bfloat16(xv);
        __nv_bfloat16 lo = __float2bfloat16(xv - __bfloat162float(hi));
        ob[3*k] = hi;
        if (ASIDE) { ob[3*k+1] = lo; ob[3*k+2] = hi; }
        else       { ob[3*k+1] = hi; ob[3*k+2] = lo; }
    }
    uint4* o = reinterpret_cast<uint4*>(out + i * 24);
    const uint4* s = reinterpret_cast<const uint4*>(ob);
    o[0] = s[0]; o[1] = s[1]; o[2] = s[2];
}

// ---------------- splitK reduce + 0.25 scale + A-side expansion -------------
__global__ void reduce_expand(const float* __restrict__ P,
                              __nv_bfloat16* __restrict__ out) {
    size_t idx = (size_t)blockIdx.x * blockDim.x + threadIdx.x;
    if (idx >= (size_t)MTOK * RK) return;
    const size_t S = (size_t)MTOK * RK;
    float s = P[idx] + P[idx + S] + P[idx + 2*S] + P[idx + 3*S];
    s *= 0.25f;                       // LORA_ALPHA / R = 16/64
    __nv_bfloat16 hi = __float2bfloat16(s);
    __nv_bfloat16 lo = __float2bfloat16(s - __bfloat162float(hi));
    out[3*idx] = hi; out[3*idx+1] = lo; out[3*idx+2] = hi;
}

// ---------------- bf16 TN GEMM (mma.sync) -----------------------------------
// MODE 0: C fp32 [M][N], LoRA K-tail supported.
// MODE 1: fused SwiGLU -> He bf16x3. B rows interleaved gate/up; tile covers
//         64 d-values (n0 is a d-offset = blockIdx.x*64). K-tail supported.
// MODE 2: splitK partial, C fp32 [SPLITK][M][64], no tail, blockIdx.z = split.
#define BM 128
#define BN 128
#define BKK 64
#define STAGES 3
#define NTH 256
#define TILE_BYTES (BM * BKK * 2)              // 16 KB
#define SMEM_BYTES (2 * STAGES * TILE_BYTES)   // 96 KB -> 2 CTAs/SM

template<int MODE>
__device__ __forceinline__ void load_tiles(uint32_t smem_u32, int stage,
                                           const __nv_bfloat16* gA,
                                           const __nv_bfloat16* gB,
                                           int m0, int n0, int N, int Ks,
                                           int kt, int tid) {
#pragma unroll
    for (int i = 0; i < 4; i++) {
        int c = tid + i * NTH;          // 0..1023 (16B chunks per operand)
        int row = c >> 3;
        int col = c & 7;
        uint32_t sw = (uint32_t)(col ^ (row & 7)) << 4;
        uint32_t da = smem_u32 + (uint32_t)stage * TILE_BYTES + row * 128 + sw;
        const void* sa = (const void*)(gA + (size_t)(m0 + row) * Ks
                                          + (size_t)kt * BKK + col * 8);
        asm volatile("cp.async.cg.shared.global [%0], [%1], 16;"
                     :: "r"(da), "l"(sa));
        int brow;
        if (MODE == 1) {                // interleave gate/up rows; n0 = d-offset
            brow = (row & 1) ? (DEX + n0 + (row >> 1)) : (n0 + (row >> 1));
        } else {
            brow = n0 + row; brow = brow < N ? brow : N - 1;  // clamp (N=64)
        }
        uint32_t db = smem_u32 + (uint32_t)(STAGES + stage) * TILE_BYTES
                               + row * 128 + sw;
        const void* sb = (const void*)(gB + (size_t)brow * Ks
                                          + (size_t)kt * BKK + col * 8);
        asm volatile("cp.async.cg.shared.global [%0], [%1], 16;"
                     :: "r"(db), "l"(sb));
    }
}

template<int MODE>
__global__ __launch_bounds__(NTH, 2) void gemm_bf16x3(
    const __nv_bfloat16* __restrict__ A,  const __nv_bfloat16* __restrict__ B,
    const __nv_bfloat16* __restrict__ A2, const __nv_bfloat16* __restrict__ B2,
    void* __restrict__ Cout, int N, int K, int Kt) {
    extern __shared__ char smem[];
    const uint32_t smem_u32 = (uint32_t)__cvta_generic_to_shared(smem);
    const int tid  = threadIdx.x;
    const int warp = tid >> 5, lane = tid & 31;
    const int wm = warp >> 2, wn = warp & 3;   // 2x4 warps -> 64x32 warp tile
    const int gid = lane >> 2, tig = lane & 3;
    const int m0 = blockIdx.y * BM;
    // MODE 1 tiles cover 64 d-values each (128 interleaved gate/up rows).
    const int n0 = blockIdx.x * ((MODE == 1) ? 64 : BN);

    float acc[4][4][4];
#pragma unroll
    for (int a = 0; a < 4; a++)
#pragma unroll
        for (int b = 0; b < 4; b++)
#pragma unroll
            for (int c = 0; c < 4; c++) acc[a][b][c] = 0.0f;

    const int a_row_in = (lane & 15);
    const int a_ch_in  = (lane >> 4);
    const int b_row_in = ((lane >> 4) << 3) + (lane & 7);
    const int b_ch_in  = ((lane >> 3) & 1);

    const int cps   = (MODE == 2) ? (K / BKK) / SPLITK : 0;
    const int koff  = (MODE == 2) ? blockIdx.z * cps : 0;
    const int nseg  = (MODE == 2) ? 1 : 2;

    for (int seg = 0; seg < nseg; seg++) {
        const __nv_bfloat16* gA = seg ? A2 : A;
        const __nv_bfloat16* gB = seg ? B2 : B;
        const int Ks = seg ? Kt : K;
        if (Ks == 0) break;
        const int ktiles = (MODE == 2) ? cps : Ks / BKK;

        for (int p = 0; p < STAGES - 1; p++) {
            if (p < ktiles)
                load_tiles<MODE>(smem_u32, p, gA, gB, m0, n0, N, Ks,
                                 koff + p, tid);
            asm volatile("cp.async.commit_group;");
        }

        for (int kt = 0; kt < ktiles; kt++) {
            asm volatile("cp.async.wait_group %0;" :: "n"(STAGES - 2));
            __syncthreads();
            int nk = kt + STAGES - 1;
            if (nk < ktiles)
                load_tiles<MODE>(smem_u32, nk % STAGES, gA, gB, m0, n0, N, Ks,
                                 koff + nk, tid);
            asm volatile("cp.async.commit_group;");

            const int st = kt % STAGES;
            const uint32_t sA = smem_u32 + (uint32_t)st * TILE_BYTES;
            const uint32_t sB = smem_u32 + (uint32_t)(STAGES + st) * TILE_BYTES;
#pragma unroll
            for (int kk = 0; kk < BKK; kk += 16) {
                uint32_t ra[4][4];
#pragma unroll
                for (int mi = 0; mi < 4; mi++) {
                    int row = wm * 64 + mi * 16 + a_row_in;
                    int ch  = (kk >> 3) + a_ch_in;
                    uint32_t ad = sA + row * 128 + ((uint32_t)(ch ^ (row & 7)) << 4);
                    asm volatile(
                        "ldmatrix.sync.aligned.m8n8.x4.shared.b16 {%0,%1,%2,%3}, [%4];"
                        : "=r"(ra[mi][0]), "=r"(ra[mi][1]),
                          "=r"(ra[mi][2]), "=r"(ra[mi][3])
                        : "r"(ad));
                }
                uint32_t rb[4][2];
#pragma unroll
                for (int p = 0; p < 2; p++) {
                    int row = wn * 32 + p * 16 + b_row_in;
                    int ch  = (kk >> 3) + b_ch_in;
                    uint32_t bd = sB + row * 128 + ((uint32_t)(ch ^ (row & 7)) << 4);
                    asm volatile(
                        "ldmatrix.sync.aligned.m8n8.x4.shared.b16 {%0,%1,%2,%3}, [%4];"
                        : "=r"(rb[2*p][0]), "=r"(rb[2*p][1]),
                          "=r"(rb[2*p+1][0]), "=r"(rb[2*p+1][1])
                        : "r"(bd));
                }
#pragma unroll
                for (int mi = 0; mi < 4; mi++)
#pragma unroll
                    for (int ni = 0; ni < 4; ni++)
                        asm volatile(
                            "mma.sync.aligned.m16n8k16.row.col.f32.bf16.bf16.f32 "
                            "{%0,%1,%2,%3}, {%4,%5,%6,%7}, {%8,%9}, {%0,%1,%2,%3};"
                            : "+f"(acc[mi][ni][0]), "+f"(acc[mi][ni][1]),
                              "+f"(acc[mi][ni][2]), "+f"(acc[mi][ni][3])
                            : "r"(ra[mi][0]), "r"(ra[mi][1]),
                              "r"(ra[mi][2]), "r"(ra[mi][3]),
                              "r"(rb[ni][0]), "r"(rb[ni][1]));
            }
        }
        asm volatile("cp.async.wait_group 0;");
        __syncthreads();
    }

    if (MODE == 0) {
        float* C = (float*)Cout;
#pragma unroll
        for (int mi = 0; mi < 4; mi++) {
            int r0 = m0 + wm * 64 + mi * 16 + gid;
#pragma unroll
            for (int ni = 0; ni < 4; ni++) {
                int c0 = n0 + wn * 32 + ni * 8 + tig * 2;
                float2 v0 = make_float2(acc[mi][ni][0], acc[mi][ni][1]);
                float2 v1 = make_float2(acc[mi][ni][2], acc[mi][ni][3]);
                *reinterpret_cast<float2*>(C + (size_t)r0 * N + c0) = v0;
                *reinterpret_cast<float2*>(C + (size_t)(r0 + 8) * N + c0) = v1;
            }
        }
    } else if (MODE == 2) {
        float* C = (float*)Cout + (size_t)blockIdx.z * MTOK * RK;
#pragma unroll
        for (int mi = 0; mi < 4; mi++) {
            int r0 = m0 + wm * 64 + mi * 16 + gid;
#pragma unroll
            for (int ni = 0; ni < 4; ni++) {
                int c0 = wn * 32 + ni * 8 + tig * 2;
                if (c0 < RK) {
                    float2 v0 = make_float2(acc[mi][ni][0], acc[mi][ni][1]);
                    float2 v1 = make_float2(acc[mi][ni][2], acc[mi][ni][3]);
                    *reinterpret_cast<float2*>(C + (size_t)r0 * RK + c0) = v0;
                    *reinterpret_cast<float2*>(C + (size_t)(r0 + 8) * RK + c0) = v1;
                }
            }
        }
    } else {
        // MODE 1: acc pair (c0,c1) = (gate,up) for local d = wn*16+ni*4+tig.
        // Stage h through smem, then coalesced bf16x3 writes.
        float* hs = reinterpret_cast<float*>(smem);   // [128][68] padded
#pragma unroll
        for (int mi = 0; mi < 4; mi++) {
            int rl = wm * 64 + mi * 16 + gid;
#pragma unroll
            for (int ni = 0; ni < 4; ni++) {
                int dl = wn * 16 + ni * 4 + tig;      // local d 0..63
                float g0 = acc[mi][ni][0], u0 = acc[mi][ni][1];
                hs[rl * 68 + dl]       = u0 * g0 / (1.0f + __expf(-g0));
                float g1 = acc[mi][ni][2], u1 = acc[mi][ni][3];
                hs[(rl + 8) * 68 + dl] = u1 * g1 / (1.0f + __expf(-g1));
            }
        }
        __syncthreads();
        __nv_bfloat16* He = (__nv_bfloat16*)Cout;
#pragma unroll
        for (int it = 0; it < 4; it++) {
            int rl  = it * 32 + (tid >> 3);
            int blk = tid & 7;
            float4 v0 = *reinterpret_cast<float4*>(&hs[rl * 68 + blk * 8]);
            float4 v1 = *reinterpret_cast<float4*>(&hs[rl * 68 + blk * 8 + 4]);
            float x[8] = {v0.x, v0.y, v0.z, v0.w, v1.x, v1.y, v1.z, v1.w};
            __nv_bfloat16 ob[24];
#pragma unroll
            for (int k = 0; k < 8; k++) {
                __nv_bfloat16 hi = __float2bfloat16(x[k]);
                __nv_bfloat16 lo = __float2bfloat16(x[k] - __bfloat162float(hi));
                ob[3*k] = hi; ob[3*k+1] = lo; ob[3*k+2] = hi;
            }
            uint4* o = reinterpret_cast<uint4*>(
                He + (size_t)(m0 + rl) * K2E + 3 * (n0 + blk * 8));
            const uint4* s = reinterpret_cast<const uint4*>(ob);
            o[0] = s[0]; o[1] = s[1]; o[2] = s[2];
        }
    }
}

// ---------------- launcher ---------------------------------------------------
extern "C" void kernel_launch(void* const* d_in, const int* in_sizes, int n_in,
                              void* d_out, int out_size) {
    const float* X   = (const float*)d_in[0];
    const float* Wgu = (const float*)d_in[1];
    const float* Agu = (const float*)d_in[2];
    const float* Bgu = (const float*)d_in[3];
    const float* Wd  = (const float*)d_in[4];
    const float* Ad  = (const float*)d_in[5];
    const float* Bd  = (const float*)d_in[6];
    float* out = (float*)d_out;

    __nv_bfloat16 *Xe, *Wgue, *Ague, *Bgue, *Wde, *Ade, *Bde, *T1e, *T2e, *He;
    float *Pk;
    cudaGetSymbolAddress((void**)&Xe,   g_Xe);
    cudaGetSymbolAddress((void**)&Wgue, g_Wgue);
    cudaGetSymbolAddress((void**)&Ague, g_Ague);
    cudaGetSymbolAddress((void**)&Bgue, g_Bgue);
    cudaGetSymbolAddress((void**)&Wde,  g_Wde);
    cudaGetSymbolAddress((void**)&Ade,  g_Ade);
    cudaGetSymbolAddress((void**)&Bde,  g_Bde);
    cudaGetSymbolAddress((void**)&Pk,   g_Pk);
    cudaGetSymbolAddress((void**)&T1e,  g_T1e);
    cudaGetSymbolAddress((void**)&T2e,  g_T2e);
    cudaGetSymbolAddress((void**)&He,   g_He);

    cudaFuncSetAttribute(gemm_bf16x3<0>,
                         cudaFuncAttributeMaxDynamicSharedMemorySize, SMEM_BYTES);
    cudaFuncSetAttribute(gemm_bf16x3<1>,
                         cudaFuncAttributeMaxDynamicSharedMemorySize, SMEM_BYTES);
    cudaFuncSetAttribute(gemm_bf16x3<2>,
                         cudaFuncAttributeMaxDynamicSharedMemorySize, SMEM_BYTES);

    const int T = 256;
    auto g8 = [&](size_t n) { return (unsigned)((n / 8 + T - 1) / T); };

    { size_t n = (size_t)MTOK * HID;
      cvt_expand8<true ><<<g8(n), T>>>(X, Xe, n/8, 1.0f); }
    { size_t n = (size_t)2 * DEX * HID;
      cvt_expand8<false><<<g8(n), T>>>(Wgu, Wgue, n/8, 1.0f); }
    { size_t n = (size_t)RK * HID;
      cvt_expand8<false><<<g8(n), T>>>(Agu, Ague, n/8, 1.0f); }
    { size_t n = (size_t)2 * DEX * RK;
      cvt_expand8<false><<<g8(n), T>>>(Bgu, Bgue, n/8, 1.0f); }
    { size_t n = (size_t)HID * DEX;
      cvt_expand8<false><<<g8(n), T>>>(Wd, Wde, n/8, 1.0f); }
    { size_t n = (size_t)RK * DEX;
      cvt_expand8<false><<<g8(n), T>>>(Ad, Ade, n/8, 1.0f); }
    { size_t n = (size_t)HID * RK;
      cvt_expand8<false><<<g8(n), T>>>(Bd, Bde, n/8, 1.0f); }

    dim3 blk(NTH);
    const unsigned gr = (unsigned)(((size_t)MTOK * RK + T - 1) / T);

    // T1 partials = X @ A_gu^T (splitK x4), then reduce+scale+expand -> T1e
    gemm_bf16x3<2><<<dim3(1, MTOK/BM, SPLITK), blk, SMEM_BYTES>>>(
        Xe, Ague, nullptr, nullptr, Pk, RK, K1E, 0);
    reduce_expand<<<gr, T>>>(Pk, T1e);

    // GEMM1 fused: He = swiglu(X @ Wgu^T + T1s @ Bgu^T), bf16x3 output
    gemm_bf16x3<1><<<dim3(DEX/64, MTOK/BM), blk, SMEM_BYTES>>>(
        Xe, Wgue, T1e, Bgue, He, 2*DEX, K1E, KRE);

    // T2 partials = H @ A_d^T (splitK x4), reduce -> T2e
    gemm_bf16x3<2><<<dim3(1, MTOK/BM, SPLITK), blk, SMEM_BYTES>>>(
        He, Ade, nullptr, nullptr, Pk, RK, K2E, 0);
    reduce_expand<<<gr, T>>>(Pk, T2e);

    // out = H @ W_d^T + T2s @ B_d^T
    gemm_bf16x3<0><<<dim3(HID/BN, MTOK/BM), blk, SMEM_BYTES>>>(
        He, Wde, T2e, Bde, out, HID, K2E, KRE);
}